// round 14
// baseline (speedup 1.0000x reference)
#include <cuda_runtime.h>
#include <cuda_fp16.h>
#include <stdint.h>

#define MAXN 50000
#define MAXE 800000
#define XD 32
#define HD 96
#define OD 64
#define PQBLK 391                 // ceil(50000/128) pq blocks
#define HBLK  645                 // edge-chain blocks (barrier participants)
#define TOTBLK (PQBLK + HBLK)     // 1036 = 7 * 148
#define NSCAN 391                 // ceil(50000/128) scan chunks

// ---- device scratch ----
__device__ __half2 g_ph[MAXN * (HD / 2)];   // p (c folded) in half2
__device__ __half2 g_qh[MAXN * (HD / 2)];   // q in half2
__device__ float   g_Z[MAXN * HD];          // relu-sum accumulator (fp32)
__device__ int     g_deg[MAXN];
__device__ int     g_off[MAXN + 1];
__device__ int     g_rank[MAXE];
__device__ int     g_srcs[MAXE];
__device__ int     g_bsum[NSCAN];
__device__ int     g_is64;
__device__ int     g_scount = 0;
__device__ volatile int g_sgen = 0;

// ---- f32x2 packed helpers (sm_103a) ----
__device__ __forceinline__ unsigned long long pack2(float lo, float hi) {
    unsigned long long d;
    asm("mov.b64 %0, {%1, %2};" : "=l"(d) : "f"(lo), "f"(hi));
    return d;
}
__device__ __forceinline__ void unpack2(float& lo, float& hi, unsigned long long v) {
    asm("mov.b64 {%0, %1}, %2;" : "=f"(lo), "=f"(hi) : "l"(v));
}
__device__ __forceinline__ unsigned long long fma2(unsigned long long a,
                                                   unsigned long long b,
                                                   unsigned long long c) {
    unsigned long long d;
    asm("fma.rn.f32x2 %0, %1, %2, %3;" : "=l"(d) : "l"(a), "l"(b), "l"(c));
    return d;
}

__device__ __forceinline__ int warp_reduce(int v) {
#pragma unroll
    for (int o = 16; o > 0; o >>= 1) v += __shfl_down_sync(0xffffffffu, v, o);
    return v;
}

// barrier among the HBLK edge-chain blocks only
__device__ __forceinline__ void hist_barrier() {
    __syncthreads();
    if (threadIdx.x == 0) {
        __threadfence();
        int gen = g_sgen;
        if (atomicAdd(&g_scount, 1) == HBLK - 1) {
            g_scount = 0;
            __threadfence();
            g_sgen = gen + 1;
        } else {
            while (g_sgen == gen) { __nanosleep(32); }
        }
        __threadfence();
    }
    __syncthreads();
}

// ---- megafused front end: pq (blocks < PQBLK) || zero->hist->scan->offsets ----
__global__ void __launch_bounds__(128, 7)
mega_kernel(const float* __restrict__ x, const float* __restrict__ scalars,
            const float* __restrict__ W1, const float* __restrict__ b1,
            const void* __restrict__ ei, int n, int e) {
    __shared__ float2 sWAB[HD * XD];    // 24KB (pq blocks only)
    __shared__ float  sc[HD];
    __shared__ int    s_any;
    __shared__ int    wpre[4];
    __shared__ int    sbase;
    const int tid = threadIdx.x;
    const int bid = blockIdx.x;

    if (bid < PQBLK) {
        for (int i = tid; i < HD * XD; i += 128) {
            int j = i >> 5, r = i & 31;
            float wB = W1[(48 + r) * HD + j];
            sWAB[i] = make_float2(W1[r * HD + j] - wB, wB);
        }
        if (tid < HD) {
            float c = b1[tid];
#pragma unroll
            for (int s = 0; s < 16; s++) c += scalars[s] * W1[(32 + s) * HD + tid];
            sc[tid] = c;
        }
        __syncthreads();

        const int node = bid * 128 + tid;
        if (node < n) {
            float xr[XD];
            const float4* xp = (const float4*)(x + (size_t)node * XD);
#pragma unroll
            for (int i = 0; i < 8; i++) {
                float4 v = __ldg(&xp[i]);
                xr[4 * i] = v.x; xr[4 * i + 1] = v.y;
                xr[4 * i + 2] = v.z; xr[4 * i + 3] = v.w;
            }
#pragma unroll 1
            for (int jc = 0; jc < 12; jc++) {
                unsigned long long acc[8];
#pragma unroll
                for (int u = 0; u < 8; u++) acc[u] = pack2(sc[jc * 8 + u], 0.0f);
#pragma unroll
                for (int r2 = 0; r2 < 16; r2++) {
                    unsigned long long xx0 = pack2(xr[2 * r2], xr[2 * r2]);
                    unsigned long long xx1 = pack2(xr[2 * r2 + 1], xr[2 * r2 + 1]);
#pragma unroll
                    for (int u = 0; u < 8; u++) {
                        ulonglong2 wv = *(const ulonglong2*)&sWAB[(jc * 8 + u) * XD + 2 * r2];
                        acc[u] = fma2(xx0, wv.x, acc[u]);
                        acc[u] = fma2(xx1, wv.y, acc[u]);
                    }
                }
                float pa[8], qa[8];
#pragma unroll
                for (int u = 0; u < 8; u++) unpack2(pa[u], qa[u], acc[u]);
                __half2 hp[4], hq[4];
#pragma unroll
                for (int u = 0; u < 4; u++) {
                    hp[u] = __floats2half2_rn(pa[2 * u], pa[2 * u + 1]);
                    hq[u] = __floats2half2_rn(qa[2 * u], qa[2 * u + 1]);
                }
                ((uint4*)g_ph)[(size_t)node * 12 + jc] = *(uint4*)hp;
                ((uint4*)g_qh)[(size_t)node * 12 + jc] = *(uint4*)hq;
            }
        }
    } else {
        const int hb = bid - PQBLK;        // 0..HBLK-1
        const int lane = tid & 31, wid = tid >> 5;

        // --- zero deg + Z, block-local dtype detect ---
        for (int i = hb * 128 + tid; i < n; i += HBLK * 128) g_deg[i] = 0;
        {
            const float4 z4 = make_float4(0.f, 0.f, 0.f, 0.f);
            float4* zp = (float4*)g_Z;
            for (int i = hb * 128 + tid; i < n * 24; i += HBLK * 128) zp[i] = z4;
        }
        if (tid == 0) s_any = 0;
        __syncthreads();
        {
            const int* ei32 = (const int*)ei;
            int a = 0;
            for (int k = tid; k < 1024; k += 128) a |= ei32[2 * k + 1];
            if (a) s_any = 1;
        }
        __syncthreads();
        const bool is64 = (s_any == 0);
        if (hb == 0 && tid == 0) g_is64 = is64 ? 1 : 0;
        const long long* p64 = (const long long*)ei;
        const int* p32 = (const int*)ei;

        hist_barrier();   // deg/Z zeroed everywhere

        // --- hist + rank ---
        for (int i = hb * 128 + tid; i < e; i += HBLK * 128) {
            int dst = is64 ? (int)p64[e + i] : p32[e + i];
            g_rank[i] = atomicAdd(&g_deg[dst], 1);
        }
        hist_barrier();   // all counts done

        // --- scan pass 1: block-local scan ---
        const int i0 = hb * 128 + tid;
        int v = 0, excl_local = 0;
        if (hb < NSCAN) {
            v = (i0 < n) ? g_deg[i0] : 0;
            int incl = v;
#pragma unroll
            for (int o = 1; o < 32; o <<= 1) {
                int t = __shfl_up_sync(0xffffffffu, incl, o);
                if (lane >= o) incl += t;
            }
            if (lane == 31) wpre[wid] = incl;
            __syncthreads();
            if (tid == 0) {
                int run = 0;
#pragma unroll
                for (int k = 0; k < 4; k++) { int t = wpre[k]; wpre[k] = run; run += t; }
                g_bsum[hb] = run;
            }
            __syncthreads();
            excl_local = wpre[wid] + incl - v;
        }
        hist_barrier();   // all bsum written

        // --- scan pass 2: global prefix + offsets ---
        if (hb < NSCAN) {
            if (tid < 32) {
                int ss = 0;
                for (int k = tid; k < hb; k += 32) ss += g_bsum[k];
                ss = warp_reduce(ss);
                if (tid == 0) sbase = ss;
            }
            __syncthreads();
            if (i0 < n) {
                int excl = sbase + excl_local;
                g_off[i0] = excl;
                if (i0 == n - 1) g_off[n] = excl + v;
            }
        }
    }
}

// ---- deterministic scatter (full width) ----
__global__ void scatter_kernel(const void* __restrict__ ei, int e) {
    int i = blockIdx.x * blockDim.x + threadIdx.x;
    if (i >= e) return;
    int src, dst;
    if (g_is64) {
        src = (int)((const long long*)ei)[i];
        dst = (int)((const long long*)ei)[e + i];
    } else {
        src = ((const int*)ei)[i];
        dst = ((const int*)ei)[e + i];
    }
    g_srcs[g_off[dst] + g_rank[i]] = src;
}

// ---- edge-split gather: each warp owns 64 contiguous sorted edges ----
__global__ void __launch_bounds__(256)
gather_kernel(int n, int e) {
    const int lane = threadIdx.x & 31;
    const int gw = blockIdx.x * 8 + (threadIdx.x >> 5);
    const int e0 = gw * 64;
    if (e0 >= e) return;
    const int e1 = min(e0 + 64, e);
    const bool act = lane < 24;

    // binary search: largest cur with off[cur] <= e0
    int lo = 0, hi = n - 1;
    while (lo < hi) {
        int mid = (lo + hi + 1) >> 1;
        if (__ldg(&g_off[mid]) <= e0) lo = mid; else hi = mid - 1;
    }
    int cur = lo;
    int nxt = __ldg(&g_off[cur + 1]);

    const uint2 zero2 = make_uint2(0u, 0u);
    uint2 pc = act ? __ldg((const uint2*)(g_ph + (size_t)cur * 48) + lane) : zero2;
    int pre = cur + 1;
    uint2 pn = (act && pre < n) ? __ldg((const uint2*)(g_ph + (size_t)pre * 48) + lane) : zero2;
    __half2 pph0 = *(__half2*)&pc.x;
    __half2 pph1 = *(__half2*)&pc.y;
    const __half2 hz = __float2half2_rn(0.f);
    float zx = 0.f, zy = 0.f, zz = 0.f, zw = 0.f;

    for (int base = e0; base < e1; base += 32) {
        const int cnt = min(32, e1 - base);
        int sreg = (lane < cnt) ? __ldg(&g_srcs[base + lane]) : 0;
        for (int k = 0; k < cnt; k += 8) {
            const int bc = min(8, cnt - k);
            uint2 v[8];
#pragma unroll
            for (int u = 0; u < 8; u++) {
                if (u < bc) {
                    int su = __shfl_sync(0xffffffffu, sreg, k + u);
                    v[u] = act ? __ldg((const uint2*)(g_qh + (size_t)su * 48) + lane)
                               : zero2;
                }
            }
#pragma unroll
            for (int u = 0; u < 8; u++) {
                if (u >= bc) break;
                const int eidx = base + k + u;
                if (eidx >= nxt) {                   // warp-uniform
                    if (act) {
                        float* zp = g_Z + (size_t)cur * HD + lane * 4;
                        atomicAdd(zp + 0, zx);
                        atomicAdd(zp + 1, zy);
                        atomicAdd(zp + 2, zz);
                        atomicAdd(zp + 3, zw);
                    }
                    zx = zy = zz = zw = 0.f;
                    cur++;
                    nxt = __ldg(&g_off[cur + 1]);
                    while (eidx >= nxt) { cur++; nxt = __ldg(&g_off[cur + 1]); }
                    pc = (cur == pre) ? pn
                       : (act ? __ldg((const uint2*)(g_ph + (size_t)cur * 48) + lane)
                              : zero2);
                    pph0 = *(__half2*)&pc.x;
                    pph1 = *(__half2*)&pc.y;
                    pre = cur + 1;
                    pn = (act && pre < n)
                       ? __ldg((const uint2*)(g_ph + (size_t)pre * 48) + lane)
                       : zero2;
                }
                __half2 h0 = __hmax2(__hadd2(pph0, *(__half2*)&v[u].x), hz);
                __half2 h1 = __hmax2(__hadd2(pph1, *(__half2*)&v[u].y), hz);
                float2 f0 = __half22float2(h0);
                float2 f1 = __half22float2(h1);
                zx += f0.x; zy += f0.y; zz += f1.x; zw += f1.y;
            }
        }
    }
    if (act) {
        float* zp = g_Z + (size_t)cur * HD + lane * 4;
        atomicAdd(zp + 0, zx);
        atomicAdd(zp + 1, zy);
        atomicAdd(zp + 2, zz);
        atomicAdd(zp + 3, zw);
    }
}

// ---- gemm: out = Z @ W2 + deg*b2, dup-broadcast z, f32x2 fma ----
__global__ void __launch_bounds__(256)
gemm_kernel(const float* __restrict__ W2, const float* __restrict__ b2,
            float* __restrict__ out, int n) {
    __shared__ unsigned long long sW2v[HD * 32];        // {W2[k][c], W2[k][c+32]}
    __shared__ unsigned long long sdup[32][HD];         // {z, z} per node/k
    __shared__ float sb2[OD];
    const int tid = threadIdx.x;
    for (int i = tid; i < HD * 32; i += 256) {
        int k = i >> 5, c = i & 31;
        sW2v[i] = pack2(W2[k * OD + c], W2[k * OD + c + 32]);
    }
    if (tid < OD) sb2[tid] = b2[tid];

    const int base = blockIdx.x * 32;
    for (int i = tid; i < 32 * HD; i += 256) {
        int nl = i / HD, k = i % HD;
        int node = base + nl;
        float z = (node < n) ? g_Z[(size_t)node * HD + k] : 0.f;
        sdup[nl][k] = pack2(z, z);
    }
    __syncthreads();

    const int w = tid >> 5, lane = tid & 31;
    const int nd0 = w * 4;
    unsigned long long acc[4];
#pragma unroll
    for (int nd = 0; nd < 4; nd++) {
        int node = base + nd0 + nd;
        int deg = 0;
        if (node < n) deg = __ldg(&g_off[node + 1]) - __ldg(&g_off[node]);
        acc[nd] = pack2((float)deg * sb2[lane], (float)deg * sb2[lane + 32]);
    }

#pragma unroll 8
    for (int k = 0; k < HD; k++) {
        unsigned long long wp = sW2v[k * 32 + lane];
        acc[0] = fma2(sdup[nd0 + 0][k], wp, acc[0]);
        acc[1] = fma2(sdup[nd0 + 1][k], wp, acc[1]);
        acc[2] = fma2(sdup[nd0 + 2][k], wp, acc[2]);
        acc[3] = fma2(sdup[nd0 + 3][k], wp, acc[3]);
    }

#pragma unroll
    for (int nd = 0; nd < 4; nd++) {
        int node = base + nd0 + nd;
        if (node < n) {
            float a0, a1;
            unpack2(a0, a1, acc[nd]);
            out[(size_t)node * OD + lane] = a0;
            out[(size_t)node * OD + lane + 32] = a1;
        }
    }
}

extern "C" void kernel_launch(void* const* d_in, const int* in_sizes, int n_in,
                              void* d_out, int out_size) {
    const float* x       = (const float*)d_in[0];
    const float* scalars = (const float*)d_in[1];
    const float* W1      = (const float*)d_in[2];
    const float* b1      = (const float*)d_in[3];
    const float* W2      = (const float*)d_in[4];
    const float* b2      = (const float*)d_in[5];
    const void*  ei      = d_in[6];
    float* out = (float*)d_out;

    int n = in_sizes[0] / XD;   // 50000
    int e = in_sizes[6] / 2;    // 800000

    mega_kernel<<<TOTBLK, 128>>>(x, scalars, W1, b1, ei, n, e);
    scatter_kernel<<<(e + 255) / 256, 256>>>(ei, e);
    int warps = (e + 63) / 64;
    gather_kernel<<<(warps + 7) / 8, 256>>>(n, e);
    gemm_kernel<<<(n + 31) / 32, 256>>>(W2, b2, out, n);
}

// round 15
// speedup vs baseline: 1.2992x; 1.2992x over previous
#include <cuda_runtime.h>
#include <cuda_fp16.h>
#include <stdint.h>

#define MAXN 50000
#define MAXE 800000
#define XD 32
#define HD 96
#define OD 64
#define PQBLK 391                 // ceil(50000/128) pq blocks
#define HBLK  645                 // edge-chain blocks (barrier participants)
#define TOTBLK (PQBLK + HBLK)     // 1036 = 7 * 148
#define NSCAN 391                 // ceil(50000/128) scan chunks

// ---- device scratch ----
__device__ __half2 g_ph[MAXN * (HD / 2)];   // p (c folded) in half2
__device__ __half2 g_qh[MAXN * (HD / 2)];   // q in half2
__device__ float   g_Z[MAXN * HD];          // relu-sum accumulator
__device__ int     g_deg[MAXN];
__device__ int     g_off[MAXN + 1];
__device__ int     g_rank[MAXE];
__device__ int     g_srcs[MAXE];
__device__ int     g_bsum[NSCAN];
__device__ int     g_scount = 0;
__device__ volatile int g_sgen = 0;

// ---- f32x2 packed helpers (sm_103a) ----
__device__ __forceinline__ unsigned long long pack2(float lo, float hi) {
    unsigned long long d;
    asm("mov.b64 %0, {%1, %2};" : "=l"(d) : "f"(lo), "f"(hi));
    return d;
}
__device__ __forceinline__ void unpack2(float& lo, float& hi, unsigned long long v) {
    asm("mov.b64 {%0, %1}, %2;" : "=f"(lo), "=f"(hi) : "l"(v));
}
__device__ __forceinline__ unsigned long long fma2(unsigned long long a,
                                                   unsigned long long b,
                                                   unsigned long long c) {
    unsigned long long d;
    asm("fma.rn.f32x2 %0, %1, %2, %3;" : "=l"(d) : "l"(a), "l"(b), "l"(c));
    return d;
}

__device__ __forceinline__ int warp_reduce(int v) {
#pragma unroll
    for (int o = 16; o > 0; o >>= 1) v += __shfl_down_sync(0xffffffffu, v, o);
    return v;
}

// barrier among the HBLK edge-chain blocks only
__device__ __forceinline__ void hist_barrier() {
    __syncthreads();
    if (threadIdx.x == 0) {
        __threadfence();
        int gen = g_sgen;
        if (atomicAdd(&g_scount, 1) == HBLK - 1) {
            g_scount = 0;
            __threadfence();
            g_sgen = gen + 1;
        } else {
            while (g_sgen == gen) { __nanosleep(32); }
        }
        __threadfence();
    }
    __syncthreads();
}

// ---- megafused front end: pq (blocks < PQBLK) || zero->hist->scan->scatter ----
__global__ void __launch_bounds__(128, 7)
mega_kernel(const float* __restrict__ x, const float* __restrict__ scalars,
            const float* __restrict__ W1, const float* __restrict__ b1,
            const void* __restrict__ ei, int n, int e) {
    __shared__ float2 sWAB[HD * XD];    // 24KB (pq blocks only)
    __shared__ float  sc[HD];
    __shared__ int    s_any;
    __shared__ int    wpre[4];
    __shared__ int    sbase;
    const int tid = threadIdx.x;
    const int bid = blockIdx.x;

    if (bid < PQBLK) {
        for (int i = tid; i < HD * XD; i += 128) {
            int j = i >> 5, r = i & 31;
            float wB = W1[(48 + r) * HD + j];
            sWAB[i] = make_float2(W1[r * HD + j] - wB, wB);
        }
        if (tid < HD) {
            float c = b1[tid];
#pragma unroll
            for (int s = 0; s < 16; s++) c += scalars[s] * W1[(32 + s) * HD + tid];
            sc[tid] = c;
        }
        __syncthreads();

        const int node = bid * 128 + tid;
        if (node < n) {
            float xr[XD];
            const float4* xp = (const float4*)(x + (size_t)node * XD);
#pragma unroll
            for (int i = 0; i < 8; i++) {
                float4 v = __ldg(&xp[i]);
                xr[4 * i] = v.x; xr[4 * i + 1] = v.y;
                xr[4 * i + 2] = v.z; xr[4 * i + 3] = v.w;
            }
#pragma unroll 1
            for (int jc = 0; jc < 12; jc++) {
                unsigned long long acc[8];
#pragma unroll
                for (int u = 0; u < 8; u++) acc[u] = pack2(sc[jc * 8 + u], 0.0f);
#pragma unroll
                for (int r2 = 0; r2 < 16; r2++) {
                    unsigned long long xx0 = pack2(xr[2 * r2], xr[2 * r2]);
                    unsigned long long xx1 = pack2(xr[2 * r2 + 1], xr[2 * r2 + 1]);
#pragma unroll
                    for (int u = 0; u < 8; u++) {
                        ulonglong2 wv = *(const ulonglong2*)&sWAB[(jc * 8 + u) * XD + 2 * r2];
                        acc[u] = fma2(xx0, wv.x, acc[u]);
                        acc[u] = fma2(xx1, wv.y, acc[u]);
                    }
                }
                float pa[8], qa[8];
#pragma unroll
                for (int u = 0; u < 8; u++) unpack2(pa[u], qa[u], acc[u]);
                __half2 hp[4], hq[4];
#pragma unroll
                for (int u = 0; u < 4; u++) {
                    hp[u] = __floats2half2_rn(pa[2 * u], pa[2 * u + 1]);
                    hq[u] = __floats2half2_rn(qa[2 * u], qa[2 * u + 1]);
                }
                ((uint4*)g_ph)[(size_t)node * 12 + jc] = *(uint4*)hp;
                ((uint4*)g_qh)[(size_t)node * 12 + jc] = *(uint4*)hq;
            }
        }
    } else {
        const int hb = bid - PQBLK;        // 0..HBLK-1
        const int lane = tid & 31, wid = tid >> 5;

        // --- zero deg + block-local dtype detect ---
        for (int i = hb * 128 + tid; i < n; i += HBLK * 128) g_deg[i] = 0;
        if (tid == 0) s_any = 0;
        __syncthreads();
        {
            const int* ei32 = (const int*)ei;
            int a = 0;
            for (int k = tid; k < 1024; k += 128) a |= ei32[2 * k + 1];
            if (a) s_any = 1;
        }
        __syncthreads();
        const bool is64 = (s_any == 0);
        const long long* p64 = (const long long*)ei;
        const int* p32 = (const int*)ei;

        hist_barrier();   // deg zeroed everywhere

        // --- hist + rank ---
        for (int i = hb * 128 + tid; i < e; i += HBLK * 128) {
            int dst = is64 ? (int)p64[e + i] : p32[e + i];
            g_rank[i] = atomicAdd(&g_deg[dst], 1);
        }
        hist_barrier();   // all counts done

        // --- scan pass 1: block-local scan of 128 deg entries ---
        const int i0 = hb * 128 + tid;
        int v = 0, excl_local = 0;
        if (hb < NSCAN) {
            v = (i0 < n) ? g_deg[i0] : 0;
            int incl = v;
#pragma unroll
            for (int o = 1; o < 32; o <<= 1) {
                int t = __shfl_up_sync(0xffffffffu, incl, o);
                if (lane >= o) incl += t;
            }
            if (lane == 31) wpre[wid] = incl;
            __syncthreads();
            if (tid == 0) {
                int run = 0;
#pragma unroll
                for (int k = 0; k < 4; k++) { int t = wpre[k]; wpre[k] = run; run += t; }
                g_bsum[hb] = run;
            }
            __syncthreads();
            excl_local = wpre[wid] + incl - v;
        }
        hist_barrier();   // all bsum written

        // --- scan pass 2: global prefix + write offsets ---
        if (hb < NSCAN) {
            if (tid < 32) {
                int ss = 0;
                for (int k = tid; k < hb; k += 32) ss += g_bsum[k];
                ss = warp_reduce(ss);
                if (tid == 0) sbase = ss;
            }
            __syncthreads();
            if (i0 < n) {
                int excl = sbase + excl_local;
                g_off[i0] = excl;
                if (i0 == n - 1) g_off[n] = excl + v;
            }
        }
        hist_barrier();   // all offsets written

        // --- deterministic scatter ---
        for (int i = hb * 128 + tid; i < e; i += HBLK * 128) {
            int src, dst;
            if (is64) { src = (int)p64[i]; dst = (int)p64[e + i]; }
            else      { src = p32[i];      dst = p32[e + i]; }
            g_srcs[g_off[dst] + g_rank[i]] = src;
        }
    }
}

// ---- gather: warp-per-node, batch-2 fp16 pair reduction ----
__global__ void __launch_bounds__(256, 6)
gather_kernel(int n) {
    const int w = threadIdx.x >> 5, lane = threadIdx.x & 31;
    const int node = blockIdx.x * 8 + w;
    if (node >= n) return;

    const int off0 = __ldg(&g_off[node]);
    const int off1 = __ldg(&g_off[node + 1]);
    const uint2 zero2 = make_uint2(0u, 0u);
    uint2 pp2 = (lane < 24)
              ? __ldg((const uint2*)(g_ph + (size_t)node * 48) + lane)
              : zero2;
    const __half2 pph0 = *(__half2*)&pp2.x;
    const __half2 pph1 = *(__half2*)&pp2.y;
    const __half2 hz = __float2half2_rn(0.f);
    float zx = 0.f, zy = 0.f, zz = 0.f, zw = 0.f;

    for (int bb = off0; bb < off1; bb += 32) {
        int cnt = min(32, off1 - bb);
        int sreg = (lane < cnt) ? __ldg(&g_srcs[bb + lane]) : 0;
        int k = 0;
        for (; k + 7 < cnt; k += 8) {
            uint2 v[8];
#pragma unroll
            for (int u = 0; u < 8; u++) {
                int su = __shfl_sync(0xffffffffu, sreg, k + u);
                v[u] = (lane < 24)
                     ? __ldg((const uint2*)(g_qh + (size_t)su * 48) + lane)
                     : zero2;
            }
#pragma unroll
            for (int u = 0; u < 8; u += 2) {
                __half2 a0 = __hmax2(__hadd2(pph0, *(__half2*)&v[u].x), hz);
                __half2 a1 = __hmax2(__hadd2(pph1, *(__half2*)&v[u].y), hz);
                __half2 b0 = __hmax2(__hadd2(pph0, *(__half2*)&v[u + 1].x), hz);
                __half2 b1 = __hmax2(__hadd2(pph1, *(__half2*)&v[u + 1].y), hz);
                __half2 s0 = __hadd2(a0, b0);
                __half2 s1 = __hadd2(a1, b1);
                float2 f0 = __half22float2(s0);
                float2 f1 = __half22float2(s1);
                zx += f0.x; zy += f0.y; zz += f1.x; zw += f1.y;
            }
        }
        for (; k < cnt; k++) {
            int su = __shfl_sync(0xffffffffu, sreg, k);
            uint2 v0 = (lane < 24)
                     ? __ldg((const uint2*)(g_qh + (size_t)su * 48) + lane)
                     : zero2;
            __half2 h0 = __hmax2(__hadd2(pph0, *(__half2*)&v0.x), hz);
            __half2 h1 = __hmax2(__hadd2(pph1, *(__half2*)&v0.y), hz);
            float2 f0 = __half22float2(h0);
            float2 f1 = __half22float2(h1);
            zx += f0.x; zy += f0.y; zz += f1.x; zw += f1.y;
        }
    }
    if (lane < 24)
        *(float4*)(g_Z + (size_t)node * HD + lane * 4) = make_float4(zx, zy, zz, zw);
}

// ---- gemm: out = Z @ W2 + deg*b2 ----
// 8 nodes/warp. W2 staged in smem packed 2-k-deep (LDS.128 per 2 k-steps);
// z read via LDG.64 warp-broadcast straight from g_Z (no sdup smem).
__global__ void __launch_bounds__(256)
gemm_kernel(const float* __restrict__ W2, const float* __restrict__ b2,
            float* __restrict__ out, int n) {
    __shared__ ulonglong2 sW2vv[(HD / 2) * 32];   // 24.5KB: {pair(2k2), pair(2k2+1)}
    __shared__ float sb2[OD];
    const int tid = threadIdx.x;
    for (int i = tid; i < (HD / 2) * 32; i += 256) {
        int k2 = i >> 5, c = i & 31;
        ulonglong2 v;
        v.x = pack2(W2[(2 * k2) * OD + c],     W2[(2 * k2) * OD + c + 32]);
        v.y = pack2(W2[(2 * k2 + 1) * OD + c], W2[(2 * k2 + 1) * OD + c + 32]);
        sW2vv[i] = v;
    }
    if (tid < OD) sb2[tid] = b2[tid];
    __syncthreads();

    const int w = tid >> 5, lane = tid & 31;
    const int base = (blockIdx.x * 8 + w) * 8;    // first of 8 nodes
    if (base >= n) return;
    const int nv = min(8, n - base);

    unsigned long long acc[8];
#pragma unroll
    for (int nd = 0; nd < 8; nd++) {
        int deg = 0;
        if (nd < nv) deg = __ldg(&g_off[base + nd + 1]) - __ldg(&g_off[base + nd]);
        acc[nd] = pack2((float)deg * sb2[lane], (float)deg * sb2[lane + 32]);
    }
    const float2* zp0 = (const float2*)(g_Z + (size_t)base * HD);

#pragma unroll 2
    for (int k2 = 0; k2 < HD / 2; k2++) {
        ulonglong2 wp = sW2vv[k2 * 32 + lane];
#pragma unroll
        for (int nd = 0; nd < 8; nd++) {
            if (nd < nv) {
                float2 zz = __ldg(zp0 + (size_t)nd * (HD / 2) + k2);  // broadcast
                acc[nd] = fma2(pack2(zz.x, zz.x), wp.x, acc[nd]);
                acc[nd] = fma2(pack2(zz.y, zz.y), wp.y, acc[nd]);
            }
        }
    }

#pragma unroll
    for (int nd = 0; nd < 8; nd++) {
        if (nd < nv) {
            float a0, a1;
            unpack2(a0, a1, acc[nd]);
            out[(size_t)(base + nd) * OD + lane] = a0;
            out[(size_t)(base + nd) * OD + lane + 32] = a1;
        }
    }
}

extern "C" void kernel_launch(void* const* d_in, const int* in_sizes, int n_in,
                              void* d_out, int out_size) {
    const float* x       = (const float*)d_in[0];
    const float* scalars = (const float*)d_in[1];
    const float* W1      = (const float*)d_in[2];
    const float* b1      = (const float*)d_in[3];
    const float* W2      = (const float*)d_in[4];
    const float* b2      = (const float*)d_in[5];
    const void*  ei      = d_in[6];
    float* out = (float*)d_out;

    int n = in_sizes[0] / XD;   // 50000
    int e = in_sizes[6] / 2;    // 800000

    mega_kernel<<<TOTBLK, 128>>>(x, scalars, W1, b1, ei, n, e);
    gather_kernel<<<(n + 7) / 8, 256>>>(n);
    gemm_kernel<<<(n + 63) / 64, 256>>>(W2, b2, out, n);
}